// round 1
// baseline (speedup 1.0000x reference)
#include <cuda_runtime.h>
#include <math.h>

#define N_TOK   4096
#define DMODEL  256
#define NHEAD   4
#define DPH     64
#define NEXP    9
#define LN_EPS  1e-5f
#define ATT_SCALE 0.25f   // (dph // num_heads) ** -0.5 = 16^-0.5

// -------- device scratch (no allocs allowed) --------
__device__ float g_q[N_TOK * DMODEL];
__device__ float g_k[N_TOK * DMODEL];
__device__ float g_v[N_TOK * DMODEL];
__device__ float g_ctx[N_TOK * DMODEL];
__device__ float g_h[N_TOK * DMODEL];
__device__ int   g_perm[N_TOK];
__device__ int   g_counts[NEXP];
__device__ int   g_offsets[NEXP + 1];
__device__ int   g_cursor[NEXP];

// -------- sort-by-label kernels --------
__global__ void k_zero() {
    int t = threadIdx.x;
    if (t < NEXP) { g_counts[t] = 0; g_cursor[t] = 0; }
}

__global__ void k_hist(const int* __restrict__ label) {
    int i = blockIdx.x * blockDim.x + threadIdx.x;
    if (i < N_TOK) atomicAdd(&g_counts[label[i]], 1);
}

__global__ void k_scan() {
    int off = 0;
    for (int e = 0; e < NEXP; e++) { g_offsets[e] = off; off += g_counts[e]; }
    g_offsets[NEXP] = off;
}

__global__ void k_scatter(const int* __restrict__ label) {
    int i = blockIdx.x * blockDim.x + threadIdx.x;
    if (i < N_TOK) {
        int l = label[i];
        int pos = g_offsets[l] + atomicAdd(&g_cursor[l], 1);
        g_perm[pos] = i;
    }
}

// -------- grouped QKV projection GEMM --------
// grid: (128 mtiles, 4 ntiles, 27 = mat*9+group). block: 256.
// Computes dst[perm(row)][col] = sum_k x[perm(row)][k] * W[g][k][col] + bias[g][col]
__global__ void k_qkv(const float* __restrict__ x,
                      const float* __restrict__ Wq, const float* __restrict__ bq,
                      const float* __restrict__ Wk, const float* __restrict__ bk,
                      const float* __restrict__ Wv, const float* __restrict__ bv)
{
    int g   = blockIdx.z % NEXP;
    int mat = blockIdx.z / NEXP;
    int goff = g_offsets[g];
    int gcnt = g_offsets[g + 1] - goff;
    int row0 = blockIdx.x * 32;
    if (row0 >= gcnt) return;
    int rows = min(32, gcnt - row0);
    int col0 = blockIdx.y * 64;

    const float* W; const float* bias; float* dst;
    if (mat == 0)      { W = Wq; bias = bq; dst = g_q; }
    else if (mat == 1) { W = Wk; bias = bk; dst = g_k; }
    else               { W = Wv; bias = bv; dst = g_v; }
    W    += (size_t)g * DMODEL * DMODEL;
    bias += g * DMODEL;

    __shared__ float Xs[32 * 33];
    __shared__ __align__(16) float Ws[32 * 64];
    __shared__ int Ts[32];

    int tid = threadIdx.x;
    if (tid < 32) Ts[tid] = (tid < rows) ? g_perm[goff + row0 + tid] : 0;
    __syncthreads();

    int ty = tid >> 4;   // 0..15 -> rows 2ty, 2ty+1
    int tx = tid & 15;   // 0..15 -> cols 4tx..4tx+3
    float acc0[4] = {0.f, 0.f, 0.f, 0.f};
    float acc1[4] = {0.f, 0.f, 0.f, 0.f};

    for (int kk0 = 0; kk0 < DMODEL; kk0 += 32) {
#pragma unroll
        for (int i = 0; i < 4; i++) {
            int idx = tid + i * 256;
            int r = idx >> 5, k = idx & 31;
            Xs[r * 33 + k] = (r < rows) ? x[(size_t)Ts[r] * DMODEL + kk0 + k] : 0.f;
        }
#pragma unroll
        for (int i = 0; i < 8; i++) {
            int idx = tid + i * 256;
            int k = idx >> 6, c = idx & 63;
            Ws[k * 64 + c] = W[(size_t)(kk0 + k) * DMODEL + col0 + c];
        }
        __syncthreads();
#pragma unroll
        for (int k = 0; k < 32; k++) {
            float a0 = Xs[(2 * ty) * 33 + k];
            float a1 = Xs[(2 * ty + 1) * 33 + k];
            float4 b = *(const float4*)&Ws[k * 64 + 4 * tx];
            acc0[0] += a0 * b.x; acc0[1] += a0 * b.y; acc0[2] += a0 * b.z; acc0[3] += a0 * b.w;
            acc1[0] += a1 * b.x; acc1[1] += a1 * b.y; acc1[2] += a1 * b.z; acc1[3] += a1 * b.w;
        }
        __syncthreads();
    }

    int c = col0 + 4 * tx;
    float b0 = bias[c], b1 = bias[c + 1], b2 = bias[c + 2], b3 = bias[c + 3];
    int r0 = 2 * ty, r1 = 2 * ty + 1;
    if (r0 < rows) {
        float* p = dst + (size_t)Ts[r0] * DMODEL + c;
        p[0] = acc0[0] + b0; p[1] = acc0[1] + b1; p[2] = acc0[2] + b2; p[3] = acc0[3] + b3;
    }
    if (r1 < rows) {
        float* p = dst + (size_t)Ts[r1] * DMODEL + c;
        p[0] = acc1[0] + b0; p[1] = acc1[1] + b1; p[2] = acc1[2] + b2; p[3] = acc1[3] + b3;
    }
}

// -------- per-group flash attention --------
// grid: (128 qtiles, 9 groups, 4 heads), block 256.
// thread: qi = tid/8 (query in tile), t8 = tid%8 -> owns dims [t8*8, t8*8+8)
__global__ void k_attn()
{
    int gq = blockIdx.y;
    int h  = blockIdx.z;
    int goff = g_offsets[gq];
    int gcnt = g_offsets[gq + 1] - goff;
    int row0 = blockIdx.x * 32;
    if (row0 >= gcnt) return;
    int rows = min(32, gcnt - row0);

    __shared__ float Qs[32 * 65];
    __shared__ float Ks[32 * 65];
    __shared__ __align__(16) float Vs[32 * 68];
    __shared__ float Ss[32 * 33];

    int tid = threadIdx.x;
    int qi = tid >> 3;
    int t8 = tid & 7;
    int d0 = t8 * 8;

    // load Q tile (zero-padded)
#pragma unroll
    for (int i = 0; i < 8; i++) {
        int idx = tid + i * 256;
        int r = idx >> 6, d = idx & 63;
        float v = 0.f;
        if (r < rows) {
            int t = g_perm[goff + row0 + r];
            v = g_q[(size_t)t * DMODEL + h * DPH + d];
        }
        Qs[r * 65 + d] = v;
    }

    float O[8] = {0.f, 0.f, 0.f, 0.f, 0.f, 0.f, 0.f, 0.f};
    float m = -INFINITY, l = 0.f;

    for (int kc0 = 0; kc0 < gcnt; kc0 += 32) {
        int kcnt = min(32, gcnt - kc0);
        __syncthreads();  // previous iter smem reads done (also orders Q writes)
#pragma unroll
        for (int i = 0; i < 8; i++) {
            int idx = tid + i * 256;
            int r = idx >> 6, d = idx & 63;
            float kv = 0.f, vv = 0.f;
            if (r < kcnt) {
                int t = g_perm[goff + kc0 + r];
                kv = g_k[(size_t)t * DMODEL + h * DPH + d];
                vv = g_v[(size_t)t * DMODEL + h * DPH + d];
            }
            Ks[r * 65 + d] = kv;
            Vs[r * 68 + d] = vv;
        }
        __syncthreads();

        // scores: thread computes kj = t8 + 8*i, i=0..3
        float s0 = 0.f, s1 = 0.f, s2 = 0.f, s3 = 0.f;
#pragma unroll
        for (int d = 0; d < 64; d++) {
            float qv = Qs[qi * 65 + d];
            s0 += qv * Ks[(t8     ) * 65 + d];
            s1 += qv * Ks[(t8 +  8) * 65 + d];
            s2 += qv * Ks[(t8 + 16) * 65 + d];
            s3 += qv * Ks[(t8 + 24) * 65 + d];
        }
        s0 = (t8      < kcnt) ? s0 * ATT_SCALE : -INFINITY;
        s1 = (t8 +  8 < kcnt) ? s1 * ATT_SCALE : -INFINITY;
        s2 = (t8 + 16 < kcnt) ? s2 * ATT_SCALE : -INFINITY;
        s3 = (t8 + 24 < kcnt) ? s3 * ATT_SCALE : -INFINITY;

        float mx = fmaxf(fmaxf(s0, s1), fmaxf(s2, s3));
        mx = fmaxf(mx, __shfl_xor_sync(0xffffffffu, mx, 1));
        mx = fmaxf(mx, __shfl_xor_sync(0xffffffffu, mx, 2));
        mx = fmaxf(mx, __shfl_xor_sync(0xffffffffu, mx, 4));
        float m_new = fmaxf(m, mx);
        float alpha = __expf(m - m_new);
        float p0 = __expf(s0 - m_new);
        float p1 = __expf(s1 - m_new);
        float p2 = __expf(s2 - m_new);
        float p3 = __expf(s3 - m_new);
        float ps = p0 + p1 + p2 + p3;
        ps += __shfl_xor_sync(0xffffffffu, ps, 1);
        ps += __shfl_xor_sync(0xffffffffu, ps, 2);
        ps += __shfl_xor_sync(0xffffffffu, ps, 4);
        l = l * alpha + ps;
        m = m_new;
#pragma unroll
        for (int j = 0; j < 8; j++) O[j] *= alpha;

        Ss[qi * 33 + t8     ] = p0;
        Ss[qi * 33 + t8 +  8] = p1;
        Ss[qi * 33 + t8 + 16] = p2;
        Ss[qi * 33 + t8 + 24] = p3;
        __syncwarp();
#pragma unroll
        for (int kj = 0; kj < 32; kj++) {
            float pv = Ss[qi * 33 + kj];
            float4 va = *(const float4*)&Vs[kj * 68 + d0];
            float4 vb = *(const float4*)&Vs[kj * 68 + d0 + 4];
            O[0] += pv * va.x; O[1] += pv * va.y; O[2] += pv * va.z; O[3] += pv * va.w;
            O[4] += pv * vb.x; O[5] += pv * vb.y; O[6] += pv * vb.z; O[7] += pv * vb.w;
        }
    }

    if (qi < rows) {
        int t = g_perm[goff + row0 + qi];
        float inv = 1.f / l;
        float* p = g_ctx + (size_t)t * DMODEL + h * DPH + d0;
#pragma unroll
        for (int j = 0; j < 8; j++) p[j] = O[j] * inv;
    }
}

// -------- output projection + residual --------
// grid: (128 mtiles, 4 ntiles). block 256. g_h = x + ctx @ Wf + bf
__global__ void k_proj(const float* __restrict__ x,
                       const float* __restrict__ Wf, const float* __restrict__ bf)
{
    int row0 = blockIdx.x * 32;
    int col0 = blockIdx.y * 64;

    __shared__ float Xs[32 * 33];
    __shared__ __align__(16) float Ws[32 * 64];

    int tid = threadIdx.x;
    int ty = tid >> 4;
    int tx = tid & 15;
    float acc0[4] = {0.f, 0.f, 0.f, 0.f};
    float acc1[4] = {0.f, 0.f, 0.f, 0.f};

    for (int kk0 = 0; kk0 < DMODEL; kk0 += 32) {
#pragma unroll
        for (int i = 0; i < 4; i++) {
            int idx = tid + i * 256;
            int r = idx >> 5, k = idx & 31;
            Xs[r * 33 + k] = g_ctx[(size_t)(row0 + r) * DMODEL + kk0 + k];
        }
#pragma unroll
        for (int i = 0; i < 8; i++) {
            int idx = tid + i * 256;
            int k = idx >> 6, c = idx & 63;
            Ws[k * 64 + c] = Wf[(size_t)(kk0 + k) * DMODEL + col0 + c];
        }
        __syncthreads();
#pragma unroll
        for (int k = 0; k < 32; k++) {
            float a0 = Xs[(2 * ty) * 33 + k];
            float a1 = Xs[(2 * ty + 1) * 33 + k];
            float4 b = *(const float4*)&Ws[k * 64 + 4 * tx];
            acc0[0] += a0 * b.x; acc0[1] += a0 * b.y; acc0[2] += a0 * b.z; acc0[3] += a0 * b.w;
            acc1[0] += a1 * b.x; acc1[1] += a1 * b.y; acc1[2] += a1 * b.z; acc1[3] += a1 * b.w;
        }
        __syncthreads();
    }

    int c = col0 + 4 * tx;
    float b0 = bf[c], b1 = bf[c + 1], b2 = bf[c + 2], b3 = bf[c + 3];
    int r0 = row0 + 2 * ty, r1 = row0 + 2 * ty + 1;
    {
        const float* xr = x + (size_t)r0 * DMODEL + c;
        float* p = g_h + (size_t)r0 * DMODEL + c;
        p[0] = acc0[0] + b0 + xr[0]; p[1] = acc0[1] + b1 + xr[1];
        p[2] = acc0[2] + b2 + xr[2]; p[3] = acc0[3] + b3 + xr[3];
    }
    {
        const float* xr = x + (size_t)r1 * DMODEL + c;
        float* p = g_h + (size_t)r1 * DMODEL + c;
        p[0] = acc1[0] + b0 + xr[0]; p[1] = acc1[1] + b1 + xr[1];
        p[2] = acc1[2] + b2 + xr[2]; p[3] = acc1[3] + b3 + xr[3];
    }
}

// -------- LayerNorm --------
__global__ void k_ln(const float* __restrict__ gamma, const float* __restrict__ beta,
                     float* __restrict__ out)
{
    int n = blockIdx.x;
    int tid = threadIdx.x;
    float v = g_h[(size_t)n * DMODEL + tid];
    float s = v, sq = v * v;
#pragma unroll
    for (int off = 16; off > 0; off >>= 1) {
        s  += __shfl_xor_sync(0xffffffffu, s, off);
        sq += __shfl_xor_sync(0xffffffffu, sq, off);
    }
    __shared__ float rs[8], rq[8];
    int w = tid >> 5;
    if ((tid & 31) == 0) { rs[w] = s; rq[w] = sq; }
    __syncthreads();
    s = 0.f; sq = 0.f;
#pragma unroll
    for (int i = 0; i < 8; i++) { s += rs[i]; sq += rq[i]; }
    float mean = s * (1.f / DMODEL);
    float var  = sq * (1.f / DMODEL) - mean * mean;
    float inv  = rsqrtf(var + LN_EPS);
    out[(size_t)n * DMODEL + tid] = gamma[tid] * (v - mean) * inv + beta[tid];
}

// -------- launch --------
extern "C" void kernel_launch(void* const* d_in, const int* in_sizes, int n_in,
                              void* d_out, int out_size)
{
    const float* x     = (const float*)d_in[0];
    const int*   label = (const int*)  d_in[1];
    const float* Wq    = (const float*)d_in[2];
    const float* bq    = (const float*)d_in[3];
    const float* Wk    = (const float*)d_in[4];
    const float* bk    = (const float*)d_in[5];
    const float* Wv    = (const float*)d_in[6];
    const float* bv    = (const float*)d_in[7];
    const float* Wf    = (const float*)d_in[8];
    const float* bf    = (const float*)d_in[9];
    const float* gamma = (const float*)d_in[10];
    const float* beta  = (const float*)d_in[11];
    float* out = (float*)d_out;

    k_zero<<<1, 32>>>();
    k_hist<<<N_TOK / 256, 256>>>(label);
    k_scan<<<1, 1>>>();
    k_scatter<<<N_TOK / 256, 256>>>(label);
    k_qkv<<<dim3(N_TOK / 32, DMODEL / 64, 3 * NEXP), 256>>>(x, Wq, bq, Wk, bk, Wv, bv);
    k_attn<<<dim3(N_TOK / 32, NEXP, NHEAD), 256>>>();
    k_proj<<<dim3(N_TOK / 32, DMODEL / 64), 256>>>(x, Wf, bf);
    k_ln<<<N_TOK, 256>>>(gamma, beta, out);
}

// round 2
// speedup vs baseline: 1.7491x; 1.7491x over previous
#include <cuda_runtime.h>
#include <math.h>

#define N_TOK   4096
#define DMODEL  256
#define NHEAD   4
#define DPH     64
#define NEXP    9
#define LN_EPS  1e-5f
#define ATT_SCALE 0.25f   // (dph // num_heads) ** -0.5 = 16^-0.5

typedef unsigned long long ull;

// -------- device scratch (sorted-domain layout) --------
__device__ float g_q[N_TOK * DMODEL];
__device__ float g_k[N_TOK * DMODEL];
__device__ float g_v[N_TOK * DMODEL];
__device__ float g_ctx[N_TOK * DMODEL];
__device__ float g_h[N_TOK * DMODEL];
__device__ int   g_perm[N_TOK];       // sorted pos -> original token
__device__ int   g_offsets[NEXP + 1];

// -------- f32x2 packed math helpers (sm_100+) --------
__device__ __forceinline__ ull fma2(ull a, ull b, ull c) {
    ull d;
    asm("fma.rn.f32x2 %0, %1, %2, %3;" : "=l"(d) : "l"(a), "l"(b), "l"(c));
    return d;
}
__device__ __forceinline__ ull pack2(float x) {
    ull d; asm("mov.b64 %0, {%1, %1};" : "=l"(d) : "f"(x)); return d;
}
__device__ __forceinline__ float2 unpack2(ull v) {
    float2 r; asm("mov.b64 {%0, %1}, %2;" : "=f"(r.x), "=f"(r.y) : "l"(v)); return r;
}

// -------- fused counting sort (1 block) --------
__global__ void k_sort(const int* __restrict__ label) {
    __shared__ int hist[NEXP], base[NEXP + 1], cur[NEXP];
    int t = threadIdx.x;
    if (t < NEXP) { hist[t] = 0; cur[t] = 0; }
    __syncthreads();
    for (int i = t; i < N_TOK; i += 1024) atomicAdd(&hist[label[i]], 1);
    __syncthreads();
    if (t == 0) {
        int off = 0;
        for (int e = 0; e < NEXP; e++) { base[e] = off; g_offsets[e] = off; off += hist[e]; }
        base[NEXP] = off; g_offsets[NEXP] = off;
    }
    __syncthreads();
    for (int i = t; i < N_TOK; i += 1024) {
        int l = label[i];
        int p = atomicAdd(&cur[l], 1);
        g_perm[base[l] + p] = i;
    }
}

// -------- grouped QKV GEMM: 128x128 tile, 8x8/thread, f32x2 --------
// grid (32, 2, 27), block 256. Output rows stored in SORTED order.
__global__ __launch_bounds__(256) void k_qkv(
    const float* __restrict__ x,
    const float* __restrict__ Wq, const float* __restrict__ bq,
    const float* __restrict__ Wk, const float* __restrict__ bk,
    const float* __restrict__ Wv, const float* __restrict__ bv)
{
    int g   = blockIdx.z % NEXP;
    int mat = blockIdx.z / NEXP;
    int goff = g_offsets[g];
    int gcnt = g_offsets[g + 1] - goff;
    int row0 = blockIdx.x * 128;
    if (row0 >= gcnt) return;
    int rows = min(128, gcnt - row0);
    int col0 = blockIdx.y * 128;

    const float* W; const float* bias; float* dst;
    if (mat == 0)      { W = Wq; bias = bq; dst = g_q; }
    else if (mat == 1) { W = Wk; bias = bk; dst = g_k; }
    else               { W = Wv; bias = bv; dst = g_v; }
    W    += (size_t)g * DMODEL * DMODEL;
    bias += g * DMODEL;

    __shared__ __align__(16) float As[16 * 128];   // [k][m] transposed
    __shared__ __align__(16) float Bs[16 * 128];   // [k][n]
    __shared__ int Ts[128];

    int tid = threadIdx.x;
    if (tid < 128) Ts[tid] = g_perm[goff + row0 + min(tid, rows - 1)];
    __syncthreads();

    int r = tid >> 4, c = tid & 15;
    ull acc[8][4];
#pragma unroll
    for (int i = 0; i < 8; i++)
#pragma unroll
        for (int j = 0; j < 4; j++) acc[i][j] = 0ull;

    int lm = tid >> 1, lseg = tid & 1;               // A loader
    const float* Arow = x + (size_t)Ts[lm] * DMODEL + lseg * 8;
    int bk_ = tid >> 4, bn = (tid & 15) * 8;         // B loader
    const float* Brow = W + (size_t)bk_ * DMODEL + col0 + bn;

    for (int kk0 = 0; kk0 < DMODEL; kk0 += 16) {
        float4 a0 = *(const float4*)(Arow + kk0);
        float4 a1 = *(const float4*)(Arow + kk0 + 4);
        float4 b0 = *(const float4*)(Brow + (size_t)kk0 * DMODEL);
        float4 b1 = *(const float4*)(Brow + (size_t)kk0 * DMODEL + 4);
        __syncthreads();   // previous compute done reading smem
        int kb = lseg * 8;
        As[(kb + 0) * 128 + lm] = a0.x; As[(kb + 1) * 128 + lm] = a0.y;
        As[(kb + 2) * 128 + lm] = a0.z; As[(kb + 3) * 128 + lm] = a0.w;
        As[(kb + 4) * 128 + lm] = a1.x; As[(kb + 5) * 128 + lm] = a1.y;
        As[(kb + 6) * 128 + lm] = a1.z; As[(kb + 7) * 128 + lm] = a1.w;
        *(float4*)&Bs[bk_ * 128 + bn]     = b0;
        *(float4*)&Bs[bk_ * 128 + bn + 4] = b1;
        __syncthreads();
#pragma unroll
        for (int k = 0; k < 16; k++) {
            float4 A0 = *(const float4*)&As[k * 128 + 4 * r];
            float4 A1 = *(const float4*)&As[k * 128 + 64 + 4 * r];
            ulonglong2 B0 = *(const ulonglong2*)&Bs[k * 128 + 4 * c];
            ulonglong2 B1 = *(const ulonglong2*)&Bs[k * 128 + 64 + 4 * c];
            float av[8] = {A0.x, A0.y, A0.z, A0.w, A1.x, A1.y, A1.z, A1.w};
#pragma unroll
            for (int i = 0; i < 8; i++) {
                ull a = pack2(av[i]);
                acc[i][0] = fma2(a, B0.x, acc[i][0]);
                acc[i][1] = fma2(a, B0.y, acc[i][1]);
                acc[i][2] = fma2(a, B1.x, acc[i][2]);
                acc[i][3] = fma2(a, B1.y, acc[i][3]);
            }
        }
    }

    float4 bias0 = *(const float4*)&bias[col0 + 4 * c];
    float4 bias1 = *(const float4*)&bias[col0 + 64 + 4 * c];
#pragma unroll
    for (int i = 0; i < 8; i++) {
        int m = (i < 4) ? (4 * r + i) : (60 + 4 * r + i);
        if (m < rows) {
            float* drow = dst + (size_t)(goff + row0 + m) * DMODEL;
            float2 p0 = unpack2(acc[i][0]), p1 = unpack2(acc[i][1]);
            float4 o0 = {p0.x + bias0.x, p0.y + bias0.y, p1.x + bias0.z, p1.y + bias0.w};
            *(float4*)&drow[col0 + 4 * c] = o0;
            float2 p2 = unpack2(acc[i][2]), p3 = unpack2(acc[i][3]);
            float4 o1 = {p2.x + bias1.x, p2.y + bias1.y, p3.x + bias1.z, p3.y + bias1.w};
            *(float4*)&drow[col0 + 64 + 4 * c] = o1;
        }
    }
}

// -------- per-group flash attention: 64x64 tiles, 4x4/thread --------
// grid (64, 9, 4), block 256, dynamic smem 69632B.
__global__ __launch_bounds__(256) void k_attn()
{
    int g = blockIdx.y, h = blockIdx.z;
    int goff = g_offsets[g];
    int gcnt = g_offsets[g + 1] - goff;
    int row0 = blockIdx.x * 64;
    if (row0 >= gcnt) return;
    int rows = min(64, gcnt - row0);

    extern __shared__ __align__(16) float sm[];
    float* Qt = sm;                  // [d][qi] pitch 68
    float* Kt = Qt + 64 * 68;        // [d][kj] pitch 68
    float* Vs = Kt + 64 * 68;        // [kj][d] pitch 68
    float* Ps = Vs + 64 * 68;        // [qi][kj] pitch 68

    int tid = threadIdx.x;
    int r = tid >> 4, c = tid & 15;
    int li = tid & 63, seg = tid >> 6, d0 = seg * 16;  // loader mapping

    // load Q transposed (once)
    {
        const float* qptr = g_q + (size_t)(goff + row0 + min(li, rows - 1)) * DMODEL + h * DPH + d0;
#pragma unroll
        for (int f = 0; f < 4; f++) {
            float4 v = *(const float4*)(qptr + 4 * f);
            Qt[(d0 + 4 * f + 0) * 68 + li] = v.x;
            Qt[(d0 + 4 * f + 1) * 68 + li] = v.y;
            Qt[(d0 + 4 * f + 2) * 68 + li] = v.z;
            Qt[(d0 + 4 * f + 3) * 68 + li] = v.w;
        }
    }

    float m_[4] = {-INFINITY, -INFINITY, -INFINITY, -INFINITY};
    float l_[4] = {0.f, 0.f, 0.f, 0.f};
    float O[4][4];
#pragma unroll
    for (int i = 0; i < 4; i++)
#pragma unroll
        for (int j = 0; j < 4; j++) O[i][j] = 0.f;

    for (int kc0 = 0; kc0 < gcnt; kc0 += 64) {
        int kcnt = min(64, gcnt - kc0);
        __syncthreads();   // prior PV reads done (first iter: Q stores ordered)
        {
            int krow = goff + kc0 + min(li, kcnt - 1);
            const float* kptr = g_k + (size_t)krow * DMODEL + h * DPH + d0;
            const float* vptr = g_v + (size_t)krow * DMODEL + h * DPH + d0;
#pragma unroll
            for (int f = 0; f < 4; f++) {
                float4 kv = *(const float4*)(kptr + 4 * f);
                Kt[(d0 + 4 * f + 0) * 68 + li] = kv.x;
                Kt[(d0 + 4 * f + 1) * 68 + li] = kv.y;
                Kt[(d0 + 4 * f + 2) * 68 + li] = kv.z;
                Kt[(d0 + 4 * f + 3) * 68 + li] = kv.w;
                float4 vv = *(const float4*)(vptr + 4 * f);
                *(float4*)&Vs[li * 68 + d0 + 4 * f] = vv;
            }
        }
        __syncthreads();

        // ---- QK^T ----
        float s[4][4];
#pragma unroll
        for (int i = 0; i < 4; i++)
#pragma unroll
            for (int j = 0; j < 4; j++) s[i][j] = 0.f;
#pragma unroll 8
        for (int d = 0; d < 64; d++) {
            float4 a = *(const float4*)&Qt[d * 68 + 4 * r];
            float4 b = *(const float4*)&Kt[d * 68 + 4 * c];
            s[0][0] += a.x * b.x; s[0][1] += a.x * b.y; s[0][2] += a.x * b.z; s[0][3] += a.x * b.w;
            s[1][0] += a.y * b.x; s[1][1] += a.y * b.y; s[1][2] += a.y * b.z; s[1][3] += a.y * b.w;
            s[2][0] += a.z * b.x; s[2][1] += a.z * b.y; s[2][2] += a.z * b.z; s[2][3] += a.z * b.w;
            s[3][0] += a.w * b.x; s[3][1] += a.w * b.y; s[3][2] += a.w * b.z; s[3][3] += a.w * b.w;
        }

        // ---- mask + online softmax (rows 4r..4r+3, reduce over 16 c-lanes) ----
        bool va0 = (4 * c + 0) < kcnt, va1 = (4 * c + 1) < kcnt;
        bool va2 = (4 * c + 2) < kcnt, va3 = (4 * c + 3) < kcnt;
#pragma unroll
        for (int i = 0; i < 4; i++) {
            s[i][0] = va0 ? s[i][0] * ATT_SCALE : -INFINITY;
            s[i][1] = va1 ? s[i][1] * ATT_SCALE : -INFINITY;
            s[i][2] = va2 ? s[i][2] * ATT_SCALE : -INFINITY;
            s[i][3] = va3 ? s[i][3] * ATT_SCALE : -INFINITY;
            float mx = fmaxf(fmaxf(s[i][0], s[i][1]), fmaxf(s[i][2], s[i][3]));
            mx = fmaxf(mx, __shfl_xor_sync(0xffffffffu, mx, 1));
            mx = fmaxf(mx, __shfl_xor_sync(0xffffffffu, mx, 2));
            mx = fmaxf(mx, __shfl_xor_sync(0xffffffffu, mx, 4));
            mx = fmaxf(mx, __shfl_xor_sync(0xffffffffu, mx, 8));
            float mn = fmaxf(m_[i], mx);
            float alpha = __expf(m_[i] - mn);
            float p0 = __expf(s[i][0] - mn), p1 = __expf(s[i][1] - mn);
            float p2 = __expf(s[i][2] - mn), p3 = __expf(s[i][3] - mn);
            s[i][0] = p0; s[i][1] = p1; s[i][2] = p2; s[i][3] = p3;
            float ps = p0 + p1 + p2 + p3;
            ps += __shfl_xor_sync(0xffffffffu, ps, 1);
            ps += __shfl_xor_sync(0xffffffffu, ps, 2);
            ps += __shfl_xor_sync(0xffffffffu, ps, 4);
            ps += __shfl_xor_sync(0xffffffffu, ps, 8);
            l_[i] = l_[i] * alpha + ps;
            m_[i] = mn;
            O[i][0] *= alpha; O[i][1] *= alpha; O[i][2] *= alpha; O[i][3] *= alpha;
            float4 pv = {p0, p1, p2, p3};
            *(float4*)&Ps[(4 * r + i) * 68 + 4 * c] = pv;
        }
        __syncthreads();

        // ---- P @ V ----
#pragma unroll 8
        for (int kj = 0; kj < 64; kj++) {
            float4 vv = *(const float4*)&Vs[kj * 68 + 4 * c];
            float p0 = Ps[(4 * r + 0) * 68 + kj];
            float p1 = Ps[(4 * r + 1) * 68 + kj];
            float p2 = Ps[(4 * r + 2) * 68 + kj];
            float p3 = Ps[(4 * r + 3) * 68 + kj];
            O[0][0] += p0 * vv.x; O[0][1] += p0 * vv.y; O[0][2] += p0 * vv.z; O[0][3] += p0 * vv.w;
            O[1][0] += p1 * vv.x; O[1][1] += p1 * vv.y; O[1][2] += p1 * vv.z; O[1][3] += p1 * vv.w;
            O[2][0] += p2 * vv.x; O[2][1] += p2 * vv.y; O[2][2] += p2 * vv.z; O[2][3] += p2 * vv.w;
            O[3][0] += p3 * vv.x; O[3][1] += p3 * vv.y; O[3][2] += p3 * vv.z; O[3][3] += p3 * vv.w;
        }
    }

#pragma unroll
    for (int i = 0; i < 4; i++) {
        int qrow = 4 * r + i;
        if (qrow < rows) {
            float inv = 1.f / l_[i];
            float4 o = {O[i][0] * inv, O[i][1] * inv, O[i][2] * inv, O[i][3] * inv};
            *(float4*)&g_ctx[(size_t)(goff + row0 + qrow) * DMODEL + h * DPH + 4 * c] = o;
        }
    }
}

// -------- output projection + residual: 64x64 tile, 4x4/thread --------
// grid (64, 4), block 256. g_h[sorted] = x[perm] + ctx[sorted] @ Wf + bf
__global__ __launch_bounds__(256) void k_proj(
    const float* __restrict__ x,
    const float* __restrict__ Wf, const float* __restrict__ bf)
{
    int row0 = blockIdx.x * 64;
    int col0 = blockIdx.y * 64;

    __shared__ __align__(16) float As[16 * 64];   // [k][m]
    __shared__ __align__(16) float Bs[16 * 64];   // [k][n]
    __shared__ int Ts[64];

    int tid = threadIdx.x;
    if (tid < 64) Ts[tid] = g_perm[row0 + tid];

    int r = tid >> 4, c = tid & 15;
    float acc[4][4];
#pragma unroll
    for (int i = 0; i < 4; i++)
#pragma unroll
        for (int j = 0; j < 4; j++) acc[i][j] = 0.f;

    int am = tid & 63, aseg = tid >> 6;           // A loader
    int bkk = tid >> 4, bn = (tid & 15) * 4;      // B loader

    for (int kk0 = 0; kk0 < DMODEL; kk0 += 16) {
        float4 av = *(const float4*)&g_ctx[(size_t)(row0 + am) * DMODEL + kk0 + aseg * 4];
        float4 bv = *(const float4*)&Wf[(size_t)(kk0 + bkk) * DMODEL + col0 + bn];
        __syncthreads();
        As[(aseg * 4 + 0) * 64 + am] = av.x;
        As[(aseg * 4 + 1) * 64 + am] = av.y;
        As[(aseg * 4 + 2) * 64 + am] = av.z;
        As[(aseg * 4 + 3) * 64 + am] = av.w;
        *(float4*)&Bs[bkk * 64 + bn] = bv;
        __syncthreads();
#pragma unroll
        for (int k = 0; k < 16; k++) {
            float4 a = *(const float4*)&As[k * 64 + 4 * r];
            float4 b = *(const float4*)&Bs[k * 64 + 4 * c];
            acc[0][0] += a.x * b.x; acc[0][1] += a.x * b.y; acc[0][2] += a.x * b.z; acc[0][3] += a.x * b.w;
            acc[1][0] += a.y * b.x; acc[1][1] += a.y * b.y; acc[1][2] += a.y * b.z; acc[1][3] += a.y * b.w;
            acc[2][0] += a.z * b.x; acc[2][1] += a.z * b.y; acc[2][2] += a.z * b.z; acc[2][3] += a.z * b.w;
            acc[3][0] += a.w * b.x; acc[3][1] += a.w * b.y; acc[3][2] += a.w * b.z; acc[3][3] += a.w * b.w;
        }
    }

    float4 bias = *(const float4*)&bf[col0 + 4 * c];
#pragma unroll
    for (int i = 0; i < 4; i++) {
        int m = 4 * r + i;
        const float* xr = x + (size_t)Ts[m] * DMODEL + col0 + 4 * c;
        float4 xv = *(const float4*)xr;
        float4 o = {acc[i][0] + bias.x + xv.x, acc[i][1] + bias.y + xv.y,
                    acc[i][2] + bias.z + xv.z, acc[i][3] + bias.w + xv.w};
        *(float4*)&g_h[(size_t)(row0 + m) * DMODEL + col0 + 4 * c] = o;
    }
}

// -------- LayerNorm (sorted row -> scatter to original) --------
__global__ void k_ln(const float* __restrict__ gamma, const float* __restrict__ beta,
                     float* __restrict__ out)
{
    int srow = blockIdx.x;
    int tid = threadIdx.x;
    float v = g_h[(size_t)srow * DMODEL + tid];
    float s = v, sq = v * v;
#pragma unroll
    for (int off = 16; off > 0; off >>= 1) {
        s  += __shfl_xor_sync(0xffffffffu, s, off);
        sq += __shfl_xor_sync(0xffffffffu, sq, off);
    }
    __shared__ float rs[8], rq[8];
    int w = tid >> 5;
    if ((tid & 31) == 0) { rs[w] = s; rq[w] = sq; }
    __syncthreads();
    s = 0.f; sq = 0.f;
#pragma unroll
    for (int i = 0; i < 8; i++) { s += rs[i]; sq += rq[i]; }
    float mean = s * (1.f / DMODEL);
    float var  = sq * (1.f / DMODEL) - mean * mean;
    float inv  = rsqrtf(var + LN_EPS);
    int orow = g_perm[srow];
    out[(size_t)orow * DMODEL + tid] = gamma[tid] * (v - mean) * inv + beta[tid];
}

// -------- launch --------
extern "C" void kernel_launch(void* const* d_in, const int* in_sizes, int n_in,
                              void* d_out, int out_size)
{
    const float* x     = (const float*)d_in[0];
    const int*   label = (const int*)  d_in[1];
    const float* Wq    = (const float*)d_in[2];
    const float* bq    = (const float*)d_in[3];
    const float* Wk    = (const float*)d_in[4];
    const float* bk    = (const float*)d_in[5];
    const float* Wv    = (const float*)d_in[6];
    const float* bv    = (const float*)d_in[7];
    const float* Wf    = (const float*)d_in[8];
    const float* bf    = (const float*)d_in[9];
    const float* gamma = (const float*)d_in[10];
    const float* beta  = (const float*)d_in[11];
    float* out = (float*)d_out;

    static bool attr_done = false;
    if (!attr_done) {
        cudaFuncSetAttribute(k_attn, cudaFuncAttributeMaxDynamicSharedMemorySize, 4 * 64 * 68 * 4);
        attr_done = true;
    }

    k_sort<<<1, 1024>>>(label);
    k_qkv<<<dim3(32, 2, 3 * NEXP), 256>>>(x, Wq, bq, Wk, bk, Wv, bv);
    k_attn<<<dim3(64, NEXP, NHEAD), 256, 4 * 64 * 68 * 4>>>();
    k_proj<<<dim3(64, 4), 256>>>(x, Wf, bf);
    k_ln<<<N_TOK, 256>>>(gamma, beta, out);
}